// round 3
// baseline (speedup 1.0000x reference)
#include <cuda_runtime.h>
#include <cuda_bf16.h>

// Shapes fixed by the problem: x[B=2048, C=16, S=2000] fp32.
// Key identity: einsum('bcs,bcm->bcs', x, softmax(...)) == x * rowsum(softmax) == x.
// So the whole q/k/attention branch is identity (to ~1e-7); the kernel only has to
// compute: out[b,j,s] = LN_j( sum_c Wp[j,c]*x[b,c,s] + bp[j] ) * gp[j] + hp[j].

#define CN   16
#define SN   2000
#define BN   2048
#define LN_EPS 1e-5f

__global__ __launch_bounds__(256) void fused_proj_ln(
    const float* __restrict__ x,
    const float* __restrict__ Wp,
    const float* __restrict__ bp,
    const float* __restrict__ gp,
    const float* __restrict__ hp,
    float* __restrict__ out)
{
    __shared__ float sW[CN * CN];
    __shared__ float sb[CN], sg[CN], sh[CN];

    const int t = threadIdx.x;
    if (t < CN * CN) sW[t] = Wp[t];
    if (t < CN) { sb[t] = bp[t]; sg[t] = gp[t]; sh[t] = hp[t]; }
    __syncthreads();

    // One thread handles 4 consecutive s positions (float4). S=2000 -> 500 groups/b.
    const unsigned GPB = SN / 4;                 // 500
    unsigned g = blockIdx.x * 256u + (unsigned)t;
    if (g >= (unsigned)BN * GPB) return;         // grid sized exactly; guard anyway
    const unsigned b  = g / GPB;
    const unsigned s4 = (g % GPB) * 4u;

    const float* xb = x + (size_t)b * (CN * SN) + s4;

    // Load the 16-channel vector for 4 s-positions. Each load is a coalesced
    // 16B-per-lane access, contiguous in s across the warp.
    float4 v[CN];
#pragma unroll
    for (int c = 0; c < CN; ++c)
        v[c] = *reinterpret_cast<const float4*>(xb + (size_t)c * SN);

    // y[j] = bp[j] + sum_c Wp[j,c] * v[c]   (16x16 matvec, 4-wide)
    float4 y[CN];
    float4 mu = make_float4(0.f, 0.f, 0.f, 0.f);
#pragma unroll
    for (int j = 0; j < CN; ++j) {
        const float bj = sb[j];
        float4 acc = make_float4(bj, bj, bj, bj);
#pragma unroll
        for (int c = 0; c < CN; ++c) {
            const float w = sW[j * CN + c];
            acc.x = fmaf(w, v[c].x, acc.x);
            acc.y = fmaf(w, v[c].y, acc.y);
            acc.z = fmaf(w, v[c].z, acc.z);
            acc.w = fmaf(w, v[c].w, acc.w);
        }
        y[j] = acc;
        mu.x += acc.x; mu.y += acc.y; mu.z += acc.z; mu.w += acc.w;
    }

    const float inv = 1.0f / (float)CN;
    mu.x *= inv; mu.y *= inv; mu.z *= inv; mu.w *= inv;

    float4 var = make_float4(0.f, 0.f, 0.f, 0.f);
#pragma unroll
    for (int j = 0; j < CN; ++j) {
        const float dx = y[j].x - mu.x;
        const float dy = y[j].y - mu.y;
        const float dz = y[j].z - mu.z;
        const float dw = y[j].w - mu.w;
        var.x = fmaf(dx, dx, var.x);
        var.y = fmaf(dy, dy, var.y);
        var.z = fmaf(dz, dz, var.z);
        var.w = fmaf(dw, dw, var.w);
    }
    float4 rs;
    rs.x = rsqrtf(var.x * inv + LN_EPS);
    rs.y = rsqrtf(var.y * inv + LN_EPS);
    rs.z = rsqrtf(var.z * inv + LN_EPS);
    rs.w = rsqrtf(var.w * inv + LN_EPS);

    float* ob = out + (size_t)b * (CN * SN) + s4;
#pragma unroll
    for (int j = 0; j < CN; ++j) {
        const float gj = sg[j];
        const float hj = sh[j];
        float4 o;
        o.x = fmaf((y[j].x - mu.x) * rs.x, gj, hj);
        o.y = fmaf((y[j].y - mu.y) * rs.y, gj, hj);
        o.z = fmaf((y[j].z - mu.z) * rs.z, gj, hj);
        o.w = fmaf((y[j].w - mu.w) * rs.w, gj, hj);
        *reinterpret_cast<float4*>(ob + (size_t)j * SN) = o;
    }
}

extern "C" void kernel_launch(void* const* d_in, const int* in_sizes, int n_in,
                              void* d_out, int out_size)
{
    // metadata order: x, Wq, bq, gq, hq, Wk, bk, gk, hk, Wp, bp, gp, hp
    const float* x  = (const float*)d_in[0];
    const float* Wp = (const float*)d_in[9];
    const float* bp = (const float*)d_in[10];
    const float* gp = (const float*)d_in[11];
    const float* hp = (const float*)d_in[12];
    float* out = (float*)d_out;

    const unsigned groups = (unsigned)BN * (SN / 4);   // 1,024,000
    const unsigned blocks = (groups + 255u) / 256u;    // 4000
    fused_proj_ln<<<blocks, 256>>>(x, Wp, bp, gp, hp, out);
}